// round 9
// baseline (speedup 1.0000x reference)
#include <cuda_runtime.h>
#include <math.h>

#define BB 64
#define LQ 32
#define OO 128
#define LK 256
#define DD 128
#define ALPHA_F 12.0f

#define NORM_BLOCKS (BB * LQ + OO * LK)  // 34816
#define DETECT_BLOCKS 32

// ---------------- scratch (no allocations allowed) ----------------
__device__ float g_qn[BB * LQ * DD];
__device__ float g_kn[OO * LK * DD];
// partial OR flags, flag-major: [0]=q off-byte, [1]=q aligned, [2]=k off-byte,
// [3]=k aligned; 32 slots each (one per detect block). Always fully written
// each launch -> no zeroing pass needed, replay-deterministic.
__device__ unsigned g_part[4][DETECT_BLOCKS];

// ============ kernel 1: L2 normalize + mask dtype scan =================
// Blocks [0, NORM_BLOCKS): normalize one row of q or k (128 threads = D).
// Blocks [NORM_BLOCKS, NORM_BLOCKS+32): scan both masks as uint4 and write
// partial OR flags. Masks may arrive as 1-byte bool or int32 (0/1): under
// little-endian int32 storage, bytes at i%4!=0 within the first N bytes are
// all zero; under u8 bool with ~10% ones, off-bytes are nonzero in practice.
// Reading only the first N bytes is safe under both interpretations.
__global__ void __launch_bounds__(128)
fused_prep_kernel(const float* __restrict__ q, const float* __restrict__ k,
                  const void* __restrict__ qm_raw,
                  const void* __restrict__ km_raw) {
    const int r = blockIdx.x;
    const int t = threadIdx.x;

    if (r >= NORM_BLOCKS) {  // ---- detect block ----
        const int db = r - NORM_BLOCKS;
        const int NQ = (BB * LQ) / 16;  // 128 uint4
        const int NK = (OO * LK) / 16;  // 2048 uint4
        const int gid = db * 128 + t;
        const int stride = DETECT_BLOCKS * 128;

        unsigned f[4] = {0u, 0u, 0u, 0u};
        const uint4* qv = (const uint4*)qm_raw;
        const uint4* kv = (const uint4*)km_raw;
        for (int i = gid; i < NQ; i += stride) {
            uint4 v = qv[i];
            f[0] |= (v.x & 0xFFFFFF00u) | (v.y & 0xFFFFFF00u) |
                    (v.z & 0xFFFFFF00u) | (v.w & 0xFFFFFF00u);
            f[1] |= (v.x | v.y | v.z | v.w) & 0xFFu;
        }
        for (int i = gid; i < NK; i += stride) {
            uint4 v = kv[i];
            f[2] |= (v.x & 0xFFFFFF00u) | (v.y & 0xFFFFFF00u) |
                    (v.z & 0xFFFFFF00u) | (v.w & 0xFFFFFF00u);
            f[3] |= (v.x | v.y | v.z | v.w) & 0xFFu;
        }
#pragma unroll
        for (int ff = 0; ff < 4; ff++)
#pragma unroll
            for (int off = 16; off; off >>= 1)
                f[ff] |= __shfl_xor_sync(0xffffffffu, f[ff], off);
        __shared__ unsigned wf[4][4];
        if ((t & 31) == 0) {
            int w = t >> 5;
#pragma unroll
            for (int ff = 0; ff < 4; ff++) wf[ff][w] = f[ff];
        }
        __syncthreads();
        if (t < 4)
            g_part[t][db] = wf[t][0] | wf[t][1] | wf[t][2] | wf[t][3];
        return;
    }

    // ---- normalize block ----
    const float* src;
    float* dst;
    if (r < BB * LQ) {
        src = q + (size_t)r * DD;
        dst = g_qn + (size_t)r * DD;
    } else {
        int r2 = r - BB * LQ;
        src = k + (size_t)r2 * DD;
        dst = g_kn + (size_t)r2 * DD;
    }
    float x = src[t];
    float ss = x * x;
#pragma unroll
    for (int off = 16; off; off >>= 1)
        ss += __shfl_xor_sync(0xffffffffu, ss, off);
    __shared__ float wred[4];
    __shared__ float s_rinv;
    if ((t & 31) == 0) wred[t >> 5] = ss;
    __syncthreads();
    if (t == 0) {
        float tot = wred[0] + wred[1] + wred[2] + wred[3];
        s_rinv = 1.0f / fmaxf(sqrtf(tot), 1e-12f);
    }
    __syncthreads();
    dst[t] = x * s_rinv;
}

// ============ kernel 2: score ==========================================
// grid (O, B), 256 threads (8 warps). Warp w owns 4 q rows; each lane owns
// 4 j columns per 128-wide k chunk (4i x 4j register tile). Online
// logsumexp per i across chunks, merged across lanes by shuffle, across
// warps by smem. Inlines flag reduction, dtype resolve, qbad, outscale.
__global__ void __launch_bounds__(256, 2)
score_kernel(const void* __restrict__ qm_raw, const void* __restrict__ km_raw,
             const float* __restrict__ ls, float* __restrict__ out) {
    const int o = blockIdx.x, b = blockIdx.y;
    const int tid = threadIdx.x;
    const int warp = tid >> 5, lane = tid & 31;

    __shared__ unsigned s_flags[4];
    __shared__ int s_skip;       // batch has a masked q token -> output 0
    __shared__ int s_k_u8;
    __shared__ float s_outscale;

    // OR-reduce the 32 partial flag slots (threads 0..127, one warp per flag)
    if (tid < 128) {
        unsigned v = g_part[warp][lane];
#pragma unroll
        for (int off = 16; off; off >>= 1)
            v |= __shfl_xor_sync(0xffffffffu, v, off);
        if (lane == 0) s_flags[warp] = v;
    }
    __syncthreads();
    if (tid == 0) {
        // nonzero off-bytes => u8; only aligned nonzeros => int32; zero => u8
        bool q_u8 = (s_flags[0] != 0u) || (s_flags[1] == 0u);
        s_k_u8 = ((s_flags[2] != 0u) || (s_flags[3] == 0u)) ? 1 : 0;
        unsigned acc;
        if (q_u8) {
            const uint4* p = (const uint4*)qm_raw;  // 32 B = 2 uint4 / batch
            uint4 a = p[b * 2], c = p[b * 2 + 1];
            acc = a.x | a.y | a.z | a.w | c.x | c.y | c.z | c.w;
        } else {
            const int* p = (const int*)qm_raw;
            acc = 0u;
#pragma unroll
            for (int i = 0; i < LQ; i++) acc |= (unsigned)p[b * LQ + i];
        }
        s_skip = acc ? 1 : 0;
        float e = fminf(expf(ls[0]), 100.0f);
        s_outscale = e / (sqrtf((float)(LQ * LK)) + 1e-6f);
    }
    __syncthreads();
    if (s_skip) {  // any masked q token -> sum over Lq hits -inf -> exact 0
        if (tid == 0) out[b * OO + o] = 0.0f;
        return;
    }

    extern __shared__ float sm[];
    float* qs = sm;            // 32 x 128
    float* ks = sm + LQ * DD;  // 128 x 132 (padded, conflict-free LDS.128)
    const int KST = 132;

    {  // q tile load (coalesced float4)
        const float4* src = (const float4*)(g_qn + (size_t)b * LQ * DD);
        float4* dst = (float4*)qs;
        for (int i = tid; i < LQ * DD / 4; i += 256) dst[i] = src[i];
    }
    const int i0 = warp * 4;
    const bool k_u8 = (s_k_u8 != 0);

    float m4[4], s4[4];
#pragma unroll
    for (int a = 0; a < 4; a++) { m4[a] = -INFINITY; s4[a] = 0.0f; }

    for (int chunk = 0; chunk < 2; chunk++) {
        const int jbase = chunk * 128;
        __syncthreads();  // qs visible (iter 0) / ks safe to overwrite (iter 1)
        {
            const float4* src =
                (const float4*)(g_kn + ((size_t)o * LK + jbase) * DD);
            for (int t = tid; t < 128 * 32; t += 256) {
                int rr = t >> 5, cc = t & 31;
                float4 v = src[t];
                *((float4*)(ks + rr * KST + cc * 4)) = v;
            }
        }
        __syncthreads();

        // this lane's 4 mask bits (overlaps with FMA loop)
        bool badj[4];
#pragma unroll
        for (int c = 0; c < 4; c++) {
            const int j = jbase + lane + 32 * c;
            badj[c] = k_u8
                          ? (((const unsigned char*)km_raw)[o * LK + j] != 0)
                          : (((const int*)km_raw)[o * LK + j] != 0);
        }

        float acc[4][4];
#pragma unroll
        for (int a = 0; a < 4; a++)
#pragma unroll
            for (int c = 0; c < 4; c++) acc[a][c] = 0.0f;

        for (int d4 = 0; d4 < 32; d4++) {
            float4 kv[4];
#pragma unroll
            for (int c = 0; c < 4; c++)
                kv[c] = *((const float4*)(ks + (lane + 32 * c) * KST + d4 * 4));
#pragma unroll
            for (int a = 0; a < 4; a++) {
                float4 qv = *((const float4*)(qs + (i0 + a) * DD + d4 * 4));
#pragma unroll
                for (int c = 0; c < 4; c++) {
                    acc[a][c] = fmaf(qv.x, kv[c].x, acc[a][c]);
                    acc[a][c] = fmaf(qv.y, kv[c].y, acc[a][c]);
                    acc[a][c] = fmaf(qv.z, kv[c].z, acc[a][c]);
                    acc[a][c] = fmaf(qv.w, kv[c].w, acc[a][c]);
                }
            }
        }
        // fold this chunk into the online logsumexp stats
#pragma unroll
        for (int c = 0; c < 4; c++) {
#pragma unroll
            for (int a = 0; a < 4; a++) {
                float v = badj[c] ? -INFINITY : ALPHA_F * acc[a][c];
                float mo = m4[a];
                float mn = fmaxf(mo, v);
                if (mn != -INFINITY) {
                    float e1 = __expf(mo - mn);  // mo=-inf -> 0
                    float e2 = (v == -INFINITY) ? 0.0f : __expf(v - mn);
                    s4[a] = s4[a] * e1 + e2;
                    m4[a] = mn;
                }
            }
        }
    }

    // merge per-row (m,s) across the 32 lanes of the warp
    float rowsum = 0.0f;
#pragma unroll
    for (int a = 0; a < 4; a++) {
        float m = m4[a], s = s4[a];
#pragma unroll
        for (int off = 16; off; off >>= 1) {
            float mo = __shfl_xor_sync(0xffffffffu, m, off);
            float so = __shfl_xor_sync(0xffffffffu, s, off);
            float mn = fmaxf(m, mo);
            if (mn == -INFINITY) {
                m = -INFINITY;
                s = 0.0f;
            } else {
                s = s * __expf(m - mn) + so * __expf(mo - mn);
                m = mn;
            }
        }
        float lse = (m == -INFINITY) ? -INFINITY : (m + __logf(s));
        rowsum += lse;  // -inf propagates (all-masked k row => (b,o) -> 0)
    }
    __shared__ float wsum[8];
    if (lane == 0) wsum[warp] = rowsum;
    __syncthreads();
    if (tid == 0) {
        float tot = 0.0f;
#pragma unroll
        for (int w = 0; w < 8; w++) tot += wsum[w];
        float res = isfinite(tot) ? (tot / ALPHA_F) * s_outscale : 0.0f;
        out[b * OO + o] = res;
    }
}

// ---------------- launch ----------------
extern "C" void kernel_launch(void* const* d_in, const int* in_sizes, int n_in,
                              void* d_out, int out_size) {
    const float* q = (const float*)d_in[0];
    const float* k = (const float*)d_in[1];
    const void* qm = d_in[2];
    const void* km = d_in[3];
    const float* ls = (const float*)d_in[4];
    float* out = (float*)d_out;

    fused_prep_kernel<<<NORM_BLOCKS + DETECT_BLOCKS, 128>>>(q, k, qm, km);

    size_t smem = (size_t)(LQ * DD + 128 * 132) * sizeof(float);  // 83968 B
    cudaFuncSetAttribute(score_kernel,
                         cudaFuncAttributeMaxDynamicSharedMemorySize,
                         (int)smem);
    dim3 grid(OO, BB);
    score_kernel<<<grid, 256, smem>>>(qm, km, ls, out);
}

// round 12
// speedup vs baseline: 1.6776x; 1.6776x over previous
#include <cuda_runtime.h>
#include <math.h>

#define BB 64
#define LQ 32
#define OO 128
#define LK 256
#define DD 128
#define ALPHA_F 12.0f
#define NPAIRS (BB * OO)  // 8192
#define GRID_SCORE 304    // ~2 CTAs/SM, single wave of resident blocks
#define KST 132           // padded k-tile stride (conflict-free LDS.128)

// ---------------- scratch (no allocations allowed) ----------------
__device__ unsigned char g_qbad[BB];  // batch has any masked q token
__device__ int g_k_u8;                // 1 => k mask is u8 bool, 0 => int32
__device__ float g_outscale;          // min(exp(ls),100)/(sqrt(Lq*Lk)+1e-6)

// ============ kernel 1: mask dtype detect + per-batch flags ============
// Single block. Masks may arrive as 1-byte bool or int32 (0/1). Under
// little-endian int32 storage, bytes at i%4!=0 within the first N bytes are
// all zero; under u8 bool with ~10% ones, off-bytes are nonzero in practice.
// Reading only the first N bytes is safe under both interpretations. The
// int32-view qbad read (4N bytes) happens only AFTER dtype is resolved.
__global__ void __launch_bounds__(256)
detect_kernel(const void* __restrict__ qm_raw, const void* __restrict__ km_raw,
              const float* __restrict__ ls) {
    __shared__ unsigned s_red[4][8];
    __shared__ int s_q_u8;
    const int t = threadIdx.x, lane = t & 31, w = t >> 5;

    unsigned f[4] = {0u, 0u, 0u, 0u};
    const uint4* qv = (const uint4*)qm_raw;
    const uint4* kv = (const uint4*)km_raw;
    for (int i = t; i < (BB * LQ) / 16; i += 256) {  // 128 uint4
        uint4 v = qv[i];
        unsigned o = v.x | v.y | v.z | v.w;
        f[0] |= o & 0xFFFFFF00u;  // off-bytes nonzero => u8
        f[1] |= o & 0xFFu;        // aligned-byte nonzero
    }
    for (int i = t; i < (OO * LK) / 16; i += 256) {  // 2048 uint4
        uint4 v = kv[i];
        unsigned o = v.x | v.y | v.z | v.w;
        f[2] |= o & 0xFFFFFF00u;
        f[3] |= o & 0xFFu;
    }
#pragma unroll
    for (int ff = 0; ff < 4; ff++)
#pragma unroll
        for (int off = 16; off; off >>= 1)
            f[ff] |= __shfl_xor_sync(0xffffffffu, f[ff], off);
    if (lane == 0) {
#pragma unroll
        for (int ff = 0; ff < 4; ff++) s_red[ff][w] = f[ff];
    }
    __syncthreads();
    if (t == 0) {
        unsigned r[4];
#pragma unroll
        for (int ff = 0; ff < 4; ff++) {
            r[ff] = 0u;
#pragma unroll
            for (int ww = 0; ww < 8; ww++) r[ff] |= s_red[ff][ww];
        }
        // nonzero off-bytes => u8; only aligned nonzeros => int32; zero => u8
        s_q_u8 = ((r[0] != 0u) || (r[1] == 0u)) ? 1 : 0;
        g_k_u8 = ((r[2] != 0u) || (r[3] == 0u)) ? 1 : 0;
        float e = fminf(expf(ls[0]), 100.0f);
        g_outscale = e / (sqrtf((float)(LQ * LK)) + 1e-6f);
    }
    __syncthreads();
    if (t < BB) {
        unsigned acc;
        if (s_q_u8) {
            const uint4* p = (const uint4*)qm_raw;  // 32 B = 2 uint4 / batch
            uint4 a = p[t * 2], c = p[t * 2 + 1];
            acc = a.x | a.y | a.z | a.w | c.x | c.y | c.z | c.w;
        } else {
            const uint4* p = (const uint4*)qm_raw;  // 128 B = 8 uint4 / batch
            acc = 0u;
#pragma unroll
            for (int i = 0; i < 8; i++) {
                uint4 v = p[t * 8 + i];
                acc |= v.x | v.y | v.z | v.w;
            }
        }
        g_qbad[t] = acc ? 1 : 0;
    }
}

// ============ kernel 2: grid-stride score =============================
// 304 blocks x 256 threads. Each block loops over pairs p = b*128+o.
// Dirty-batch pairs: write 0 (whole row is exactly 0: any masked q token
// makes the Lq-sum hit -inf). Clean pairs: load raw q/k tiles to smem,
// compute per-row 1/||.|| by warp shuffle, fold both rinvs into the logit
// scale after the dot product (algebraically identical to normalizing
// inputs), online logsumexp over Lk.
__global__ void __launch_bounds__(256, 2)
score_kernel(const float* __restrict__ q, const float* __restrict__ k,
             const void* __restrict__ km_raw, float* __restrict__ out) {
    const int tid = threadIdx.x;
    const int warp = tid >> 5, lane = tid & 31;

    __shared__ unsigned char s_qbad[BB];
    __shared__ int s_k_u8;
    __shared__ float s_outscale;
    __shared__ float wsum[8];

    if (tid < BB) s_qbad[tid] = g_qbad[tid];
    if (tid == 0) {
        s_k_u8 = g_k_u8;
        s_outscale = g_outscale;
    }
    __syncthreads();
    const bool k_u8 = (s_k_u8 != 0);

    extern __shared__ float sm[];
    float* qs = sm;             // 32 x 128 raw q tile
    float* ks = sm + LQ * DD;   // 128 x 132 raw k tile (padded)
    float* rks = ks + 128 * KST;  // 128 k-row rinvs

    for (int p = blockIdx.x; p < NPAIRS; p += GRID_SCORE) {
        const int b = p >> 7, o = p & (OO - 1);
        if (s_qbad[b]) {
            if (tid == 0) out[p] = 0.0f;
            continue;
        }

        __syncthreads();  // prior pair's reads of qs done before overwrite
        {  // raw q tile load (coalesced float4)
            const float4* src = (const float4*)(q + (size_t)b * LQ * DD);
            float4* dst = (float4*)qs;
            for (int i = tid; i < LQ * DD / 4; i += 256) dst[i] = src[i];
        }
        __syncthreads();

        // per-warp q-row rinvs: warp w owns rows w*4..w*4+3
        const int i0 = warp * 4;
        float rq[4];
#pragma unroll
        for (int a = 0; a < 4; a++) {
            float4 v = *((const float4*)(qs + (i0 + a) * DD + lane * 4));
            float ss = v.x * v.x + v.y * v.y + v.z * v.z + v.w * v.w;
#pragma unroll
            for (int off = 16; off; off >>= 1)
                ss += __shfl_xor_sync(0xffffffffu, ss, off);
            rq[a] = 1.0f / fmaxf(sqrtf(ss), 1e-12f);
        }

        float m4[4], s4[4];
#pragma unroll
        for (int a = 0; a < 4; a++) { m4[a] = -INFINITY; s4[a] = 0.0f; }

        for (int chunk = 0; chunk < 2; chunk++) {
            const int jbase = chunk * 128;
            __syncthreads();  // prior chunk's ks/rks reads complete
            {  // raw k tile load
                const float4* src =
                    (const float4*)(k + ((size_t)o * LK + jbase) * DD);
                for (int t = tid; t < 128 * 32; t += 256) {
                    int rr = t >> 5, cc = t & 31;
                    float4 v = src[t];
                    *((float4*)(ks + rr * KST + cc * 4)) = v;
                }
            }
            __syncthreads();

            // k-row rinvs: warp w owns rows w*16..w*16+15
#pragma unroll
            for (int a = 0; a < 16; a++) {
                int row = warp * 16 + a;
                float4 v = *((const float4*)(ks + row * KST + lane * 4));
                float ss = v.x * v.x + v.y * v.y + v.z * v.z + v.w * v.w;
#pragma unroll
                for (int off = 16; off; off >>= 1)
                    ss += __shfl_xor_sync(0xffffffffu, ss, off);
                if (lane == 0) rks[row] = 1.0f / fmaxf(sqrtf(ss), 1e-12f);
            }
            __syncthreads();

            float rk4[4];
            bool badj[4];
#pragma unroll
            for (int c = 0; c < 4; c++) {
                rk4[c] = rks[lane + 32 * c];
                const int j = jbase + lane + 32 * c;
                badj[c] =
                    k_u8 ? (((const unsigned char*)km_raw)[o * LK + j] != 0)
                         : (((const int*)km_raw)[o * LK + j] != 0);
            }

            float acc[4][4];
#pragma unroll
            for (int a = 0; a < 4; a++)
#pragma unroll
                for (int c = 0; c < 4; c++) acc[a][c] = 0.0f;

            for (int d4 = 0; d4 < 32; d4++) {
                float4 kvv[4];
#pragma unroll
                for (int c = 0; c < 4; c++)
                    kvv[c] = *((const float4*)(ks + (lane + 32 * c) * KST +
                                               d4 * 4));
#pragma unroll
                for (int a = 0; a < 4; a++) {
                    float4 qv =
                        *((const float4*)(qs + (i0 + a) * DD + d4 * 4));
#pragma unroll
                    for (int c = 0; c < 4; c++) {
                        acc[a][c] = fmaf(qv.x, kvv[c].x, acc[a][c]);
                        acc[a][c] = fmaf(qv.y, kvv[c].y, acc[a][c]);
                        acc[a][c] = fmaf(qv.z, kvv[c].z, acc[a][c]);
                        acc[a][c] = fmaf(qv.w, kvv[c].w, acc[a][c]);
                    }
                }
            }
            // fold chunk into online logsumexp; rinvs folded into the scale
#pragma unroll
            for (int c = 0; c < 4; c++) {
#pragma unroll
                for (int a = 0; a < 4; a++) {
                    float sc = ALPHA_F * rq[a] * rk4[c];
                    float v = badj[c] ? -INFINITY : acc[a][c] * sc;
                    float mo = m4[a];
                    float mn = fmaxf(mo, v);
                    if (mn != -INFINITY) {
                        float e1 = __expf(mo - mn);  // mo=-inf -> 0
                        float e2 = (v == -INFINITY) ? 0.0f : __expf(v - mn);
                        s4[a] = s4[a] * e1 + e2;
                        m4[a] = mn;
                    }
                }
            }
        }

        // merge per-row (m,s) across the 32 lanes of the warp
        float rowsum = 0.0f;
#pragma unroll
        for (int a = 0; a < 4; a++) {
            float m = m4[a], s = s4[a];
#pragma unroll
            for (int off = 16; off; off >>= 1) {
                float mo = __shfl_xor_sync(0xffffffffu, m, off);
                float so = __shfl_xor_sync(0xffffffffu, s, off);
                float mn = fmaxf(m, mo);
                if (mn == -INFINITY) {
                    m = -INFINITY;
                    s = 0.0f;
                } else {
                    s = s * __expf(m - mn) + so * __expf(mo - mn);
                    m = mn;
                }
            }
            float lse = (m == -INFINITY) ? -INFINITY : (m + __logf(s));
            rowsum += lse;  // -inf propagates (all-masked k row => 0)
        }
        if (lane == 0) wsum[warp] = rowsum;
        __syncthreads();
        if (tid == 0) {
            float tot = 0.0f;
#pragma unroll
            for (int w = 0; w < 8; w++) tot += wsum[w];
            float res = isfinite(tot) ? (tot / ALPHA_F) * s_outscale : 0.0f;
            out[p] = res;
        }
    }
}

// ---------------- launch ----------------
extern "C" void kernel_launch(void* const* d_in, const int* in_sizes, int n_in,
                              void* d_out, int out_size) {
    const float* q = (const float*)d_in[0];
    const float* k = (const float*)d_in[1];
    const void* qm = d_in[2];
    const void* km = d_in[3];
    const float* ls = (const float*)d_in[4];
    float* out = (float*)d_out;

    detect_kernel<<<1, 256>>>(qm, km, ls);

    // qs 4096 + ks 128*132 + rks 128 floats = 84480 B
    size_t smem = (size_t)(LQ * DD + 128 * KST + 128) * sizeof(float);
    cudaFuncSetAttribute(score_kernel,
                         cudaFuncAttributeMaxDynamicSharedMemorySize,
                         (int)smem);
    score_kernel<<<GRID_SCORE, 256, smem>>>(q, k, km, out);
}